// round 10
// baseline (speedup 1.0000x reference)
#include <cuda_runtime.h>
#include <mma.h>
#include <cstdint>

using namespace nvcuda;

#define SEQ   2048
#define BATCH 64
#define INDIM 512
#define HDIM  512
#define NCOMB 1536   /* 2H (gates) + H (cand) */

// ---------------- scratch (device globals; no allocations allowed) ----------------
__device__ float    g_Xbuf[SEQ * BATCH * NCOMB];   // x@Wg_x | x@Wc_x  (fp32, no bias)
__device__ float    g_hA  [BATCH * HDIM];          // tf32-rounded h_{t-1} (A operand)
__device__ float    g_rh  [BATCH * HDIM];          // tf32-rounded r*h    (A operand)
__device__ float    g_z   [BATCH * HDIM];          // z gate (fp32)
__device__ float    g_hcur[BATCH * HDIM];          // exact fp32 h state
__device__ unsigned g_bar [4 * 32];                // per-group barrier counters (padded)

// ---------------- helpers ----------------
__device__ __forceinline__ unsigned ldcv_u32(const unsigned* p) {
    unsigned v;
    asm volatile("ld.global.cv.u32 %0, [%1];" : "=r"(v) : "l"(p));
    return v;
}

// Group barrier: monotonic counter, target = barno*16. Writer release via
// __threadfence(); reader-side __threadfence() emits CCTL.IVALL (L1D invalidate)
// so subsequent plain LDGs see other SMs' writes.
__device__ __forceinline__ void group_barrier(int g, unsigned target) {
    __syncthreads();
    if (threadIdx.x == 0) {
        __threadfence();
        atomicAdd(&g_bar[g * 32], 1u);
        while (ldcv_u32(&g_bar[g * 32]) < target) __nanosleep(64);
        __threadfence();   // acquire: invalidate L1D before the phase's loads
    }
    __syncthreads();
}

// ---------------- kernel 0: reset state + barrier counters ----------------
__global__ void reset_kernel(const float* __restrict__ h0) {
    int i = blockIdx.x * blockDim.x + threadIdx.x;
    if (i < BATCH * HDIM) {
        float v = h0[i];
        g_hcur[i] = v;
        g_hA[i]   = wmma::__float_to_tf32(v);
    }
    if (i < 4 * 32) g_bar[i] = 0u;
}

// ---------------- kernel 1: Xbuf = x @ [Wg_x | Wc_x]  (tf32 wmma GEMM) ----------
// M = SEQ*BATCH = 131072, N = 1536, K = 512. BM=128, BN=64, BK=32, 256 threads.
__global__ __launch_bounds__(256) void gemm_x_kernel(
    const float* __restrict__ x,
    const float* __restrict__ Wg,
    const float* __restrict__ Wc)
{
    __shared__ float As[128][36];   // padded (ldm 36, mult of 4)
    __shared__ float Bs[32][68];    // padded (ldm 68, mult of 4)

    const int n0  = blockIdx.x * 64;
    const int m0  = blockIdx.y * 128;
    const int tid = threadIdx.x;
    const int w   = tid >> 5;
    const int wm  = w & 3;          // 4 row-blocks of 32
    const int wn  = w >> 2;         // 2 col-blocks of 32

    wmma::fragment<wmma::accumulator, 16, 16, 8, float> acc[2][2];
#pragma unroll
    for (int i = 0; i < 2; i++)
#pragma unroll
        for (int j = 0; j < 2; j++) wmma::fill_fragment(acc[i][j], 0.0f);

    const float* Bsrc;
    int ldb, ncol0;
    if (n0 < 1024) { Bsrc = Wg; ldb = 1024; ncol0 = n0; }          // Wg_x cols
    else           { Bsrc = Wc; ldb = 512;  ncol0 = n0 - 1024; }   // Wc_x cols

    for (int k0 = 0; k0 < 512; k0 += 32) {
        __syncthreads();
        // stage A tile (128x32) with RN tf32 rounding
#pragma unroll
        for (int li = 0; li < 4; li++) {
            int lin = tid + li * 256;            // 0..1023 float4 slots
            int r   = lin >> 3;
            int kc  = (lin & 7) * 4;
            float4 v = *(const float4*)(x + (size_t)(m0 + r) * 512 + k0 + kc);
            As[r][kc + 0] = wmma::__float_to_tf32(v.x);
            As[r][kc + 1] = wmma::__float_to_tf32(v.y);
            As[r][kc + 2] = wmma::__float_to_tf32(v.z);
            As[r][kc + 3] = wmma::__float_to_tf32(v.w);
        }
        // stage B tile (32x64)
#pragma unroll
        for (int li = 0; li < 2; li++) {
            int lin = tid + li * 256;            // 0..511 float4 slots
            int kr  = lin >> 4;
            int nc  = (lin & 15) * 4;
            float4 v = *(const float4*)(Bsrc + (size_t)(k0 + kr) * ldb + ncol0 + nc);
            Bs[kr][nc + 0] = wmma::__float_to_tf32(v.x);
            Bs[kr][nc + 1] = wmma::__float_to_tf32(v.y);
            Bs[kr][nc + 2] = wmma::__float_to_tf32(v.z);
            Bs[kr][nc + 3] = wmma::__float_to_tf32(v.w);
        }
        __syncthreads();
#pragma unroll
        for (int kk = 0; kk < 4; kk++) {
            wmma::fragment<wmma::matrix_a, 16, 16, 8, wmma::precision::tf32, wmma::row_major> a[2];
            wmma::fragment<wmma::matrix_b, 16, 16, 8, wmma::precision::tf32, wmma::row_major> b[2];
#pragma unroll
            for (int i = 0; i < 2; i++)
                wmma::load_matrix_sync(a[i], &As[wm * 32 + i * 16][kk * 8], 36);
#pragma unroll
            for (int j = 0; j < 2; j++)
                wmma::load_matrix_sync(b[j], &Bs[kk * 8][wn * 32 + j * 16], 68);
#pragma unroll
            for (int i = 0; i < 2; i++)
#pragma unroll
                for (int j = 0; j < 2; j++)
                    wmma::mma_sync(acc[i][j], a[i], b[j], acc[i][j]);
        }
    }

#pragma unroll
    for (int i = 0; i < 2; i++)
#pragma unroll
        for (int j = 0; j < 2; j++)
            wmma::store_matrix_sync(
                g_Xbuf + (size_t)(m0 + wm * 32 + i * 16) * NCOMB + n0 + wn * 32 + j * 16,
                acc[i][j], NCOMB, wmma::mem_row_major);
}

// ---------------- kernel 2: persistent recurrent scan ----------------
// 4 groups x 16 CTAs; group g owns batches [16g, 16g+16). CTA r in group:
//   phase A: gate cols [64r, 64r+64) of 1024  (4 warps x 16 cols, K=512)
//   phase B: cand cols [32r, 32r+32) of 512   (warps 0-1)
// Recurrent weights live in SMEM (tf32-rounded) for the whole kernel.
#define LD_WG 68
#define LD_WC 36
#define SMEM_BYTES (512 * LD_WG * 4 + 512 * LD_WC * 4 + 16 * 68 * 4)   // 217344

__global__ __launch_bounds__(128) void gru_scan_kernel(
    const float* __restrict__ Wg,
    const float* __restrict__ Wc,
    const float* __restrict__ bg,
    const float* __restrict__ bc,
    float* __restrict__ out)
{
    extern __shared__ float sh[];
    float* WgS = sh;                        // [512][LD_WG]
    float* WcS = sh + 512 * LD_WG;          // [512][LD_WC]
    float* scr = WcS + 512 * LD_WC;         // [16][68] scratch

    const int g   = blockIdx.x >> 4;
    const int r   = blockIdx.x & 15;
    const int tid = threadIdx.x;
    const int w   = tid >> 5;
    const int b0  = g * 16;                 // batch base
    const int gc0 = r * 64;                 // gate col base (0..1023)
    const int cc0 = r * 32;                 // cand col base (0..511)

    // one-time weight staging (RN tf32 rounding)
    for (int lin = tid; lin < 512 * 64; lin += 128) {
        int k = lin >> 6, j = lin & 63;
        WgS[k * LD_WG + j] = wmma::__float_to_tf32(Wg[(size_t)(INDIM + k) * 1024 + gc0 + j]);
    }
    for (int lin = tid; lin < 512 * 32; lin += 128) {
        int k = lin >> 5, j = lin & 31;
        WcS[k * LD_WC + j] = wmma::__float_to_tf32(Wc[(size_t)(INDIM + k) * 512 + cc0 + j]);
    }
    __syncthreads();

    unsigned barno = 0;

    for (int t = 0; t < SEQ; t++) {
        // ---- phase A: gates = Xg + h @ Wg_h ----
        {
            wmma::fragment<wmma::accumulator, 16, 16, 8, float> acc;
            wmma::fill_fragment(acc, 0.0f);
            const float* aptr = g_hA + (size_t)b0 * 512;
#pragma unroll 4
            for (int kk = 0; kk < 64; kk++) {
                wmma::fragment<wmma::matrix_a, 16, 16, 8, wmma::precision::tf32, wmma::row_major> a;
                wmma::fragment<wmma::matrix_b, 16, 16, 8, wmma::precision::tf32, wmma::row_major> b;
                wmma::load_matrix_sync(a, aptr + kk * 8, 512);
                wmma::load_matrix_sync(b, WgS + kk * 8 * LD_WG + w * 16, LD_WG);
                wmma::mma_sync(acc, a, b, acc);
            }
            wmma::store_matrix_sync(scr + w * 16, acc, 68, wmma::mem_row_major);
        }
        __syncthreads();
        {
            const float* Xrow = g_Xbuf + (size_t)(t * 64 + b0) * NCOMB;
#pragma unroll
            for (int e = 0; e < 8; e++) {
                int idx = tid + e * 128;              // 0..1023
                int b   = idx >> 6;
                int j   = idx & 63;
                int col = gc0 + j;
                float gate = scr[b * 68 + j] + Xrow[(size_t)b * NCOMB + col] + bg[col];
                float s = 1.0f / (1.0f + __expf(-gate));
                int brow = b0 + b;
                if (col < 512) {
                    g_z[brow * 512 + col] = s;                      // z gate
                } else {
                    int jh = col - 512;                             // r gate -> r*h
                    float rh = s * g_hcur[brow * 512 + jh];
                    g_rh[brow * 512 + jh] = wmma::__float_to_tf32(rh);
                }
            }
        }
        barno++;
        group_barrier(g, barno * 16);

        // ---- phase B: cand = tanh(Xc + (r*h) @ Wc_h); h update ----
        if (w < 2) {
            wmma::fragment<wmma::accumulator, 16, 16, 8, float> acc;
            wmma::fill_fragment(acc, 0.0f);
            const float* aptr = g_rh + (size_t)b0 * 512;
#pragma unroll 4
            for (int kk = 0; kk < 64; kk++) {
                wmma::fragment<wmma::matrix_a, 16, 16, 8, wmma::precision::tf32, wmma::row_major> a;
                wmma::fragment<wmma::matrix_b, 16, 16, 8, wmma::precision::tf32, wmma::row_major> b;
                wmma::load_matrix_sync(a, aptr + kk * 8, 512);
                wmma::load_matrix_sync(b, WcS + kk * 8 * LD_WC + w * 16, LD_WC);
                wmma::mma_sync(acc, a, b, acc);
            }
            wmma::store_matrix_sync(scr + w * 16, acc, 36, wmma::mem_row_major);
        }
        __syncthreads();
        {
            const float* Xrow = g_Xbuf + (size_t)(t * 64 + b0) * NCOMB + 1024;
#pragma unroll
            for (int e = 0; e < 4; e++) {
                int idx = tid + e * 128;              // 0..511
                int b   = idx >> 5;
                int j   = idx & 31;
                int c   = cc0 + j;
                int brow = b0 + b;
                float cand = tanhf(scr[b * 36 + j] + Xrow[(size_t)b * NCOMB + c] + bc[c]);
                float z  = g_z[brow * 512 + c];
                float hp = g_hcur[brow * 512 + c];
                float hn = (1.0f - z) * hp + z * cand;
                out[(size_t)(t * 64 + brow) * 512 + c] = hn;
                g_hcur[brow * 512 + c] = hn;
                g_hA[brow * 512 + c]   = wmma::__float_to_tf32(hn);
                if (t == SEQ - 1)
                    out[(size_t)SEQ * 64 * 512 + brow * 512 + c] = hn;   // h_last
            }
        }
        barno++;
        group_barrier(g, barno * 16);
    }
}

// ---------------- launch ----------------
extern "C" void kernel_launch(void* const* d_in, const int* in_sizes, int n_in,
                              void* d_out, int out_size)
{
    const float* x  = (const float*)d_in[0];
    const float* h0 = (const float*)d_in[1];
    const float* Wg = (const float*)d_in[2];
    const float* bg = (const float*)d_in[3];
    const float* Wc = (const float*)d_in[4];
    const float* bc = (const float*)d_in[5];
    float* out = (float*)d_out;

    cudaFuncSetAttribute(gru_scan_kernel,
                         cudaFuncAttributeMaxDynamicSharedMemorySize, SMEM_BYTES);

    reset_kernel<<<128, 256>>>(h0);
    gemm_x_kernel<<<dim3(24, 1024), 256>>>(x, Wg, Wc);
    gru_scan_kernel<<<64, 128, SMEM_BYTES>>>(Wg, Wc, bg, bc, out);
}

// round 11
// speedup vs baseline: 4.0629x; 4.0629x over previous
#include <cuda_runtime.h>
#include <mma.h>
#include <cstdint>

using namespace nvcuda;

#define SEQ   2048
#define BATCH 64
#define INDIM 512
#define HDIM  512
#define NCOMB 1536   /* 2H (gates) + H (cand) */

// ---------------- scratch (device globals; no allocations allowed) ----------------
__device__ float    g_Xbuf[SEQ * BATCH * NCOMB];   // x@Wg_x | x@Wc_x  (fp32, no bias)
__device__ float    g_hA  [BATCH * HDIM];          // tf32-rounded h_{t-1} (A operand)
__device__ float    g_rh  [BATCH * HDIM];          // tf32-rounded r*h    (A operand)
__device__ float    g_z   [BATCH * HDIM];          // z gate (fp32)
__device__ float    g_hcur[BATCH * HDIM];          // fp32 h state (for cross-CTA r*h)
__device__ unsigned g_bar [4 * 32];                // per-group barrier counters (padded)

// ---------------- sync helpers (no membar/IVALL in the hot loop) ----------------
__device__ __forceinline__ void red_release_add(unsigned* p, unsigned v) {
    asm volatile("red.release.gpu.global.add.u32 [%0], %1;" :: "l"(p), "r"(v) : "memory");
}
__device__ __forceinline__ unsigned ld_acquire_u32(const unsigned* p) {
    unsigned v;
    asm volatile("ld.acquire.gpu.global.u32 %0, [%1];" : "=r"(v) : "l"(p) : "memory");
    return v;
}
// 32-CTA group barrier. Writers: weak STGs then release-red. Readers: acquire
// spin; subsequent exchange loads use __ldcg (L2), so no L1 invalidate needed.
__device__ __forceinline__ void group_barrier(int g, unsigned target) {
    __syncthreads();
    if (threadIdx.x == 0) {
        red_release_add(&g_bar[g * 32], 1u);
        while (ld_acquire_u32(&g_bar[g * 32]) < target) { }
    }
    __syncthreads();
}

// ---------------- kernel 0: reset state + barrier counters ----------------
__global__ void reset_kernel(const float* __restrict__ h0) {
    int i = blockIdx.x * blockDim.x + threadIdx.x;
    if (i < BATCH * HDIM) {
        float v = h0[i];
        g_hcur[i] = v;
        g_hA[i]   = wmma::__float_to_tf32(v);
    }
    if (i < 4 * 32) g_bar[i] = 0u;
}

// ---------------- kernel 1: Xbuf = x @ [Wg_x | Wc_x]  (tf32 wmma GEMM) ----------
// M = 131072, N = 1536, K = 512. BM=128, BN=64, BK=32, 256 threads.
__global__ __launch_bounds__(256) void gemm_x_kernel(
    const float* __restrict__ x,
    const float* __restrict__ Wg,
    const float* __restrict__ Wc)
{
    __shared__ float As[128][36];
    __shared__ float Bs[32][68];

    const int n0  = blockIdx.x * 64;
    const int m0  = blockIdx.y * 128;
    const int tid = threadIdx.x;
    const int w   = tid >> 5;
    const int wm  = w & 3;
    const int wn  = w >> 2;

    wmma::fragment<wmma::accumulator, 16, 16, 8, float> acc[2][2];
#pragma unroll
    for (int i = 0; i < 2; i++)
#pragma unroll
        for (int j = 0; j < 2; j++) wmma::fill_fragment(acc[i][j], 0.0f);

    const float* Bsrc;
    int ldb, ncol0;
    if (n0 < 1024) { Bsrc = Wg; ldb = 1024; ncol0 = n0; }
    else           { Bsrc = Wc; ldb = 512;  ncol0 = n0 - 1024; }

    for (int k0 = 0; k0 < 512; k0 += 32) {
        __syncthreads();
#pragma unroll
        for (int li = 0; li < 4; li++) {
            int lin = tid + li * 256;
            int r   = lin >> 3;
            int kc  = (lin & 7) * 4;
            float4 v = *(const float4*)(x + (size_t)(m0 + r) * 512 + k0 + kc);
            As[r][kc + 0] = wmma::__float_to_tf32(v.x);
            As[r][kc + 1] = wmma::__float_to_tf32(v.y);
            As[r][kc + 2] = wmma::__float_to_tf32(v.z);
            As[r][kc + 3] = wmma::__float_to_tf32(v.w);
        }
#pragma unroll
        for (int li = 0; li < 2; li++) {
            int lin = tid + li * 256;
            int kr  = lin >> 4;
            int nc  = (lin & 15) * 4;
            float4 v = *(const float4*)(Bsrc + (size_t)(k0 + kr) * ldb + ncol0 + nc);
            Bs[kr][nc + 0] = wmma::__float_to_tf32(v.x);
            Bs[kr][nc + 1] = wmma::__float_to_tf32(v.y);
            Bs[kr][nc + 2] = wmma::__float_to_tf32(v.z);
            Bs[kr][nc + 3] = wmma::__float_to_tf32(v.w);
        }
        __syncthreads();
#pragma unroll
        for (int kk = 0; kk < 4; kk++) {
            wmma::fragment<wmma::matrix_a, 16, 16, 8, wmma::precision::tf32, wmma::row_major> a[2];
            wmma::fragment<wmma::matrix_b, 16, 16, 8, wmma::precision::tf32, wmma::row_major> b[2];
#pragma unroll
            for (int i = 0; i < 2; i++)
                wmma::load_matrix_sync(a[i], &As[wm * 32 + i * 16][kk * 8], 36);
#pragma unroll
            for (int j = 0; j < 2; j++)
                wmma::load_matrix_sync(b[j], &Bs[kk * 8][wn * 32 + j * 16], 68);
#pragma unroll
            for (int i = 0; i < 2; i++)
#pragma unroll
                for (int j = 0; j < 2; j++)
                    wmma::mma_sync(acc[i][j], a[i], b[j], acc[i][j]);
        }
    }

#pragma unroll
    for (int i = 0; i < 2; i++)
#pragma unroll
        for (int j = 0; j < 2; j++)
            wmma::store_matrix_sync(
                g_Xbuf + (size_t)(m0 + wm * 32 + i * 16) * NCOMB + n0 + wn * 32 + j * 16,
                acc[i][j], NCOMB, wmma::mem_row_major);
}

// ---------------- kernel 2: persistent recurrent scan ----------------
// 4 groups x 32 CTAs (128 total). Group g owns batches [16g,16g+16).
// CTA r in group: gate cols [32r,32r+32) of 1024; cand cols [16r,16r+16) of 512.
// Weights tf32-rounded in SMEM; A operand staged to SMEM per phase.
#define LD_HS 520
#define SMEM_FLOATS (512*36 + 512*20 + 16*LD_HS + 4*16*20)
#define SMEM_BYTES  (SMEM_FLOATS * 4)          /* 153088 */

__global__ __launch_bounds__(128) void gru_scan_kernel(
    const float* __restrict__ Wg,
    const float* __restrict__ Wc,
    const float* __restrict__ bg,
    const float* __restrict__ bc,
    float* __restrict__ out)
{
    extern __shared__ float sh[];
    float* WgS = sh;                       // [512][36]  gate weight slice
    float* WcS = WgS + 512 * 36;           // [512][20]  cand weight slice
    float* hS  = WcS + 512 * 20;           // [16][520]  staged A operand
    float* scr = hS  + 16 * LD_HS;         // [4][16][20] warp partials

    const int g   = blockIdx.x >> 5;
    const int r   = blockIdx.x & 31;
    const int tid = threadIdx.x;
    const int w   = tid >> 5;
    const int b0  = g * 16;

    // one-time weight staging (RN tf32 rounding)
    for (int lin = tid; lin < 512 * 32; lin += 128) {
        int k = lin >> 5, j = lin & 31;
        WgS[k * 36 + j] = wmma::__float_to_tf32(Wg[(size_t)(INDIM + k) * 1024 + 32 * r + j]);
    }
    for (int lin = tid; lin < 512 * 16; lin += 128) {
        int k = lin >> 4, j = lin & 15;
        WcS[k * 20 + j] = wmma::__float_to_tf32(Wc[(size_t)(INDIM + k) * 512 + 16 * r + j]);
    }

    // per-thread constants: biases + own-column h state in registers
    float bgr[4], bcr[2], hreg[2];
    int   gb[4], gj[4];                    // gate epilogue (b, j)
    int   cb[2], cj[2];                    // cand epilogue (b, j)
#pragma unroll
    for (int e = 0; e < 4; e++) {
        int idx = tid + e * 128;
        gb[e] = idx >> 5; gj[e] = idx & 31;
        bgr[e] = bg[32 * r + gj[e]];
    }
#pragma unroll
    for (int e = 0; e < 2; e++) {
        int idx = tid + e * 128;
        cb[e] = idx >> 4; cj[e] = idx & 15;
        bcr[e] = bc[16 * r + cj[e]];
        hreg[e] = g_hcur[(size_t)(b0 + cb[e]) * 512 + 16 * r + cj[e]];
    }
    __syncthreads();

    const int nt = w >> 1;                 // phase-A n-tile (0/1)
    const int kh = w & 1;                  // phase-A K half
    unsigned barno = 0;

#pragma unroll 1
    for (int t = 0; t < SEQ; t++) {
        const float* Xrow = g_Xbuf + (size_t)(t * 64 + b0) * NCOMB;

        // ---- prefetch (overlaps staging + mma) ----
        float xg[4], hpv[4];
#pragma unroll
        for (int e = 0; e < 4; e++)
            xg[e] = __ldcs(Xrow + (size_t)gb[e] * NCOMB + 32 * r + gj[e]);
        if (r >= 16) {
#pragma unroll
            for (int e = 0; e < 4; e++)
                hpv[e] = __ldcg(&g_hcur[(size_t)(b0 + gb[e]) * 512 + 32 * (r - 16) + gj[e]]);
        }
        float xc[2];
#pragma unroll
        for (int e = 0; e < 2; e++)
            xc[e] = __ldcs(Xrow + (size_t)cb[e] * NCOMB + 1024 + 16 * r + cj[e]);

        // ---- stage h (tf32) tile 16x512 into SMEM, coalesced L2 loads ----
        {
            const float* src = g_hA + (size_t)b0 * 512;
#pragma unroll
            for (int s = tid; s < 2048; s += 128) {
                int b = s >> 7, c4 = s & 127;
                float4 v = __ldcg((const float4*)(src + (size_t)b * 512 + c4 * 4));
                *(float4*)(hS + b * LD_HS + c4 * 4) = v;
            }
        }
        __syncthreads();

        // ---- phase A mma: gates = h @ WgS  (2 n-tiles x 2 K-halves, dual acc) ----
        {
            wmma::fragment<wmma::accumulator, 16, 16, 8, float> a0, a1;
            wmma::fill_fragment(a0, 0.0f);
            wmma::fill_fragment(a1, 0.0f);
#pragma unroll
            for (int kk = 0; kk < 32; kk += 2) {
                int k0 = (kh * 32 + kk) * 8;
                wmma::fragment<wmma::matrix_a, 16, 16, 8, wmma::precision::tf32, wmma::row_major> af;
                wmma::fragment<wmma::matrix_b, 16, 16, 8, wmma::precision::tf32, wmma::row_major> bf;
                wmma::load_matrix_sync(af, hS + k0, LD_HS);
                wmma::load_matrix_sync(bf, WgS + k0 * 36 + nt * 16, 36);
                wmma::mma_sync(a0, af, bf, a0);
                wmma::load_matrix_sync(af, hS + k0 + 8, LD_HS);
                wmma::load_matrix_sync(bf, WgS + (k0 + 8) * 36 + nt * 16, 36);
                wmma::mma_sync(a1, af, bf, a1);
            }
#pragma unroll
            for (int i = 0; i < a0.num_elements; i++) a0.x[i] += a1.x[i];
            wmma::store_matrix_sync(scr + w * 320, a0, 20, wmma::mem_row_major);
        }
        __syncthreads();

        // ---- phase A epilogue: sigmoid; z -> g_z, r*h -> g_rh ----
#pragma unroll
        for (int e = 0; e < 4; e++) {
            int b = gb[e], j = gj[e];
            int jt = j >> 4, jj = j & 15;
            float gsum = scr[(2 * jt) * 320 + b * 20 + jj]
                       + scr[(2 * jt + 1) * 320 + b * 20 + jj]
                       + xg[e] + bgr[e];
            float s = 1.0f / (1.0f + __expf(-gsum));
            if (r < 16) {
                g_z[(size_t)(b0 + b) * 512 + 32 * r + j] = s;
            } else {
                float rh = s * hpv[e];
                g_rh[(size_t)(b0 + b) * 512 + 32 * (r - 16) + j] = wmma::__float_to_tf32(rh);
            }
        }
        barno++;
        group_barrier(g, barno * 32);

        // ---- prefetch z for own cand cols ----
        float zv[2];
#pragma unroll
        for (int e = 0; e < 2; e++)
            zv[e] = __ldcg(&g_z[(size_t)(b0 + cb[e]) * 512 + 16 * r + cj[e]]);

        // ---- stage r*h tile into SMEM ----
        {
            const float* src = g_rh + (size_t)b0 * 512;
#pragma unroll
            for (int s = tid; s < 2048; s += 128) {
                int b = s >> 7, c4 = s & 127;
                float4 v = __ldcg((const float4*)(src + (size_t)b * 512 + c4 * 4));
                *(float4*)(hS + b * LD_HS + c4 * 4) = v;
            }
        }
        __syncthreads();

        // ---- phase B mma: cand = (r*h) @ WcS  (1 n-tile, 4-way K-split) ----
        {
            wmma::fragment<wmma::accumulator, 16, 16, 8, float> a0, a1;
            wmma::fill_fragment(a0, 0.0f);
            wmma::fill_fragment(a1, 0.0f);
#pragma unroll
            for (int kk = 0; kk < 16; kk += 2) {
                int k0 = (w * 16 + kk) * 8;
                wmma::fragment<wmma::matrix_a, 16, 16, 8, wmma::precision::tf32, wmma::row_major> af;
                wmma::fragment<wmma::matrix_b, 16, 16, 8, wmma::precision::tf32, wmma::row_major> bf;
                wmma::load_matrix_sync(af, hS + k0, LD_HS);
                wmma::load_matrix_sync(bf, WcS + k0 * 20, 20);
                wmma::mma_sync(a0, af, bf, a0);
                wmma::load_matrix_sync(af, hS + k0 + 8, LD_HS);
                wmma::load_matrix_sync(bf, WcS + (k0 + 8) * 20, 20);
                wmma::mma_sync(a1, af, bf, a1);
            }
#pragma unroll
            for (int i = 0; i < a0.num_elements; i++) a0.x[i] += a1.x[i];
            wmma::store_matrix_sync(scr + w * 320, a0, 20, wmma::mem_row_major);
        }
        __syncthreads();

        // ---- phase B epilogue: tanh, h update, outputs ----
#pragma unroll
        for (int e = 0; e < 2; e++) {
            int b = cb[e], j = cj[e];
            int c = 16 * r + j;
            float csum = scr[b * 20 + j] + scr[320 + b * 20 + j]
                       + scr[640 + b * 20 + j] + scr[960 + b * 20 + j]
                       + xc[e] + bcr[e];
            float cand = tanhf(csum);
            float z  = zv[e];
            float hn = (1.0f - z) * hreg[e] + z * cand;
            hreg[e] = hn;
            size_t gidx = (size_t)(b0 + b) * 512 + c;
            out[(size_t)(t * 64 + b0 + b) * 512 + c] = hn;
            g_hcur[gidx] = hn;
            g_hA[gidx]   = wmma::__float_to_tf32(hn);
            if (t == SEQ - 1)
                out[(size_t)SEQ * 64 * 512 + gidx] = hn;
        }
        barno++;
        group_barrier(g, barno * 32);
    }
}

// ---------------- launch ----------------
extern "C" void kernel_launch(void* const* d_in, const int* in_sizes, int n_in,
                              void* d_out, int out_size)
{
    const float* x  = (const float*)d_in[0];
    const float* h0 = (const float*)d_in[1];
    const float* Wg = (const float*)d_in[2];
    const float* bg = (const float*)d_in[3];
    const float* Wc = (const float*)d_in[4];
    const float* bc = (const float*)d_in[5];
    float* out = (float*)d_out;

    cudaFuncSetAttribute(gru_scan_kernel,
                         cudaFuncAttributeMaxDynamicSharedMemorySize, SMEM_BYTES);

    reset_kernel<<<128, 256>>>(h0);
    gemm_x_kernel<<<dim3(24, 1024), 256>>>(x, Wg, Wc);
    gru_scan_kernel<<<128, 128, SMEM_BYTES>>>(Wg, Wc, bg, bc, out);
}

// round 15
// speedup vs baseline: 5.7623x; 1.4183x over previous
#include <cuda_runtime.h>
#include <mma.h>
#include <cstdint>

using namespace nvcuda;

#define SEQ   2048
#define BATCH 64
#define INDIM 512
#define HDIM  512
#define NCOMB 1536   /* 2H (gates) + H (cand) */

// ---------------- scratch (device globals; no allocations allowed) ----------------
__device__ float    g_Xbuf[SEQ * BATCH * NCOMB];   // x@Wg_x | x@Wc_x  (fp32, no bias)
__device__ float    g_hA  [BATCH * HDIM];          // tf32-rounded h_{t-1} (A operand)
__device__ float    g_rh  [BATCH * HDIM];          // tf32-rounded r*h    (A operand)
__device__ float    g_z   [BATCH * HDIM];          // z gate (fp32)
__device__ float    g_hcur[BATCH * HDIM];          // fp32 h state
__device__ unsigned g_bar [4 * 32];                // per-group barrier counters (padded)

// ---------------- helpers ----------------
__device__ __forceinline__ unsigned f2tf32(float f) {   // RN tf32 rounding, b32 container
    unsigned u;
    asm("cvt.rna.tf32.f32 %0, %1;" : "=r"(u) : "f"(f));
    return u;
}
__device__ __forceinline__ void red_release_add(unsigned* p, unsigned v) {
    asm volatile("red.release.gpu.global.add.u32 [%0], %1;" :: "l"(p), "r"(v) : "memory");
}
__device__ __forceinline__ unsigned ld_acquire_u32(const unsigned* p) {
    unsigned v;
    asm volatile("ld.acquire.gpu.global.u32 %0, [%1];" : "=r"(v) : "l"(p) : "memory");
    return v;
}
__device__ __forceinline__ void group_barrier(int g, unsigned target) {
    __syncthreads();
    if (threadIdx.x == 0) {
        red_release_add(&g_bar[g * 32], 1u);
        while (ld_acquire_u32(&g_bar[g * 32]) < target) { }
    }
    __syncthreads();
}
__device__ __forceinline__ void mma_tf32(float* c, unsigned a0, unsigned a1,
                                         unsigned a2, unsigned a3,
                                         unsigned b0, unsigned b1) {
    asm volatile(
        "mma.sync.aligned.m16n8k8.row.col.f32.tf32.tf32.f32 "
        "{%0,%1,%2,%3}, {%4,%5,%6,%7}, {%8,%9}, {%0,%1,%2,%3};\n"
        : "+f"(c[0]), "+f"(c[1]), "+f"(c[2]), "+f"(c[3])
        : "r"(a0), "r"(a1), "r"(a2), "r"(a3), "r"(b0), "r"(b1));
}

// ---------------- kernel 0: reset state + barrier counters ----------------
__global__ void reset_kernel(const float* __restrict__ h0) {
    int i = blockIdx.x * blockDim.x + threadIdx.x;
    if (i < BATCH * HDIM) {
        float v = h0[i];
        g_hcur[i] = v;
        g_hA[i]   = __uint_as_float(f2tf32(v));
    }
    if (i < 4 * 32) g_bar[i] = 0u;
}

// ---------------- kernel 1: Xbuf = x @ [Wg_x | Wc_x]  (tf32 wmma GEMM) ----------
__global__ __launch_bounds__(256) void gemm_x_kernel(
    const float* __restrict__ x,
    const float* __restrict__ Wg,
    const float* __restrict__ Wc)
{
    __shared__ float As[128][36];
    __shared__ float Bs[32][68];

    const int n0  = blockIdx.x * 64;
    const int m0  = blockIdx.y * 128;
    const int tid = threadIdx.x;
    const int w   = tid >> 5;
    const int wm  = w & 3;
    const int wn  = w >> 2;

    wmma::fragment<wmma::accumulator, 16, 16, 8, float> acc[2][2];
#pragma unroll
    for (int i = 0; i < 2; i++)
#pragma unroll
        for (int j = 0; j < 2; j++) wmma::fill_fragment(acc[i][j], 0.0f);

    const float* Bsrc;
    int ldb, ncol0;
    if (n0 < 1024) { Bsrc = Wg; ldb = 1024; ncol0 = n0; }
    else           { Bsrc = Wc; ldb = 512;  ncol0 = n0 - 1024; }

    for (int k0 = 0; k0 < 512; k0 += 32) {
        __syncthreads();
#pragma unroll
        for (int li = 0; li < 4; li++) {
            int lin = tid + li * 256;
            int r   = lin >> 3;
            int kc  = (lin & 7) * 4;
            float4 v = *(const float4*)(x + (size_t)(m0 + r) * 512 + k0 + kc);
            As[r][kc + 0] = wmma::__float_to_tf32(v.x);
            As[r][kc + 1] = wmma::__float_to_tf32(v.y);
            As[r][kc + 2] = wmma::__float_to_tf32(v.z);
            As[r][kc + 3] = wmma::__float_to_tf32(v.w);
        }
#pragma unroll
        for (int li = 0; li < 2; li++) {
            int lin = tid + li * 256;
            int kr  = lin >> 4;
            int nc  = (lin & 15) * 4;
            float4 v = *(const float4*)(Bsrc + (size_t)(k0 + kr) * ldb + ncol0 + nc);
            Bs[kr][nc + 0] = wmma::__float_to_tf32(v.x);
            Bs[kr][nc + 1] = wmma::__float_to_tf32(v.y);
            Bs[kr][nc + 2] = wmma::__float_to_tf32(v.z);
            Bs[kr][nc + 3] = wmma::__float_to_tf32(v.w);
        }
        __syncthreads();
#pragma unroll
        for (int kk = 0; kk < 4; kk++) {
            wmma::fragment<wmma::matrix_a, 16, 16, 8, wmma::precision::tf32, wmma::row_major> a[2];
            wmma::fragment<wmma::matrix_b, 16, 16, 8, wmma::precision::tf32, wmma::row_major> b[2];
#pragma unroll
            for (int i = 0; i < 2; i++)
                wmma::load_matrix_sync(a[i], &As[wm * 32 + i * 16][kk * 8], 36);
#pragma unroll
            for (int j = 0; j < 2; j++)
                wmma::load_matrix_sync(b[j], &Bs[kk * 8][wn * 32 + j * 16], 68);
#pragma unroll
            for (int i = 0; i < 2; i++)
#pragma unroll
                for (int j = 0; j < 2; j++)
                    wmma::mma_sync(acc[i][j], a[i], b[j], acc[i][j]);
        }
    }

#pragma unroll
    for (int i = 0; i < 2; i++)
#pragma unroll
        for (int j = 0; j < 2; j++)
            wmma::store_matrix_sync(
                g_Xbuf + (size_t)(m0 + wm * 32 + i * 16) * NCOMB + n0 + wn * 32 + j * 16,
                acc[i][j], NCOMB, wmma::mem_row_major);
}

// ---------------- kernel 2: persistent recurrent scan ----------------
// 4 groups x 32 CTAs (128 total), 256 threads (8 warps) per CTA.
// Group g owns batches [16g,16g+16). CTA r: gate cols [32r,32r+32),
// cand cols [16r,16r+16). Recurrent weights live in REGISTERS as mma
// B fragments (gathered once). A operand staged to SMEM per phase.
#define LD_HS 516

__global__ __launch_bounds__(256) void gru_scan_kernel(
    const float* __restrict__ Wg,
    const float* __restrict__ Wc,
    const float* __restrict__ bg,
    const float* __restrict__ bc,
    float* __restrict__ out)
{
    __shared__ float hS[16 * LD_HS];     // staged A operand (tf32 bits as float)
    __shared__ float scr[8 * 320];       // per-warp 16x16 partials, pitch 20

    const int g    = blockIdx.x >> 5;
    const int r    = blockIdx.x & 31;
    const int tid  = threadIdx.x;
    const int w    = tid >> 5;
    const int lane = tid & 31;
    const int lg   = lane >> 2;          // mma "groupID" 0..7
    const int tig  = lane & 3;           // thread-in-group 0..3
    const int b0   = g * 16;

    const int nt = w & 1;                // phase-A n-tile (cols 16*nt)
    const int kq = w >> 1;               // phase-A K-quarter (0..3)

    // ---- persistent B fragments (gathered once, tf32-rounded) ----
    unsigned bA[16][2][2];               // phase A: 16 k8-steps x 2 n8 x 2 regs
    {
        const int cbase = 32 * r + 16 * nt;
#pragma unroll
        for (int ks = 0; ks < 16; ks++) {
            int kb = INDIM + kq * 128 + ks * 8;
#pragma unroll
            for (int s = 0; s < 2; s++) {
                int cc = cbase + 8 * s + lg;
                bA[ks][s][0] = f2tf32(__ldg(Wg + (size_t)(kb + tig)     * 1024 + cc));
                bA[ks][s][1] = f2tf32(__ldg(Wg + (size_t)(kb + tig + 4) * 1024 + cc));
            }
        }
    }
    unsigned bB[8][2][2];                // phase B: 8 k8-steps x 2 n8 x 2 regs
    {
        const int cbase = 16 * r;
#pragma unroll
        for (int ks = 0; ks < 8; ks++) {
            int kb = INDIM + w * 64 + ks * 8;
#pragma unroll
            for (int s = 0; s < 2; s++) {
                int cc = cbase + 8 * s + lg;
                bB[ks][s][0] = f2tf32(__ldg(Wc + (size_t)(kb + tig)     * 512 + cc));
                bB[ks][s][1] = f2tf32(__ldg(Wc + (size_t)(kb + tig + 4) * 512 + cc));
            }
        }
    }

    // ---- per-thread epilogue constants ----
    float bgr[2];
    int   gbb[2], gj[2];
#pragma unroll
    for (int e = 0; e < 2; e++) {
        int idx = tid + e * 256;
        gbb[e] = idx >> 5; gj[e] = idx & 31;
        bgr[e] = bg[32 * r + gj[e]];
    }
    const int cbb = tid >> 4, cjj = tid & 15;
    const float bcr = bc[16 * r + cjj];
    float hreg = g_hcur[(size_t)(b0 + cbb) * 512 + 16 * r + cjj];

    unsigned barno = 0;

#pragma unroll 1
    for (int t = 0; t < SEQ; t++) {
        const float* Xrow = g_Xbuf + (size_t)(t * 64 + b0) * NCOMB;

        // ---- prefetch (overlaps staging + mma) ----
        float xg[2], hpv[2];
#pragma unroll
        for (int e = 0; e < 2; e++)
            xg[e] = __ldcs(Xrow + (size_t)gbb[e] * NCOMB + 32 * r + gj[e]);
        if (r >= 16) {
#pragma unroll
            for (int e = 0; e < 2; e++)
                hpv[e] = __ldcg(&g_hcur[(size_t)(b0 + gbb[e]) * 512 + 32 * (r - 16) + gj[e]]);
        }
        float xc = __ldcs(Xrow + (size_t)cbb * NCOMB + 1024 + 16 * r + cjj);

        // ---- stage h (tf32) 16x512 into SMEM ----
        {
            const float* src = g_hA + (size_t)b0 * 512;
#pragma unroll
            for (int s = tid; s < 2048; s += 256) {
                int b = s >> 7, c4 = s & 127;
                float4 v = __ldcg((const float4*)(src + (size_t)b * 512 + c4 * 4));
                *(float4*)(hS + b * LD_HS + c4 * 4) = v;
            }
        }
        __syncthreads();

        // ---- phase A mma: gates = h @ Wg_h (warp = n-tile nt, K-quarter kq) ----
        {
            float acc[2][4] = {};
#pragma unroll
            for (int ks = 0; ks < 16; ks++) {
                int k0 = kq * 128 + ks * 8;
                unsigned a0 = __float_as_uint(hS[lg * LD_HS + k0 + tig]);
                unsigned a1 = __float_as_uint(hS[(lg + 8) * LD_HS + k0 + tig]);
                unsigned a2 = __float_as_uint(hS[lg * LD_HS + k0 + tig + 4]);
                unsigned a3 = __float_as_uint(hS[(lg + 8) * LD_HS + k0 + tig + 4]);
                mma_tf32(acc[0], a0, a1, a2, a3, bA[ks][0][0], bA[ks][0][1]);
                mma_tf32(acc[1], a0, a1, a2, a3, bA[ks][1][0], bA[ks][1][1]);
            }
            float* sw = scr + w * 320;
#pragma unroll
            for (int s = 0; s < 2; s++) {
                sw[lg * 20 + s * 8 + 2 * tig]           = acc[s][0];
                sw[lg * 20 + s * 8 + 2 * tig + 1]       = acc[s][1];
                sw[(lg + 8) * 20 + s * 8 + 2 * tig]     = acc[s][2];
                sw[(lg + 8) * 20 + s * 8 + 2 * tig + 1] = acc[s][3];
            }
        }
        __syncthreads();

        // ---- phase A epilogue ----
#pragma unroll
        for (int e = 0; e < 2; e++) {
            int b = gbb[e], j = gj[e];
            int ntj = j >> 4, jj = j & 15;
            float gsum = xg[e] + bgr[e];
#pragma unroll
            for (int q = 0; q < 4; q++)
                gsum += scr[(2 * q + ntj) * 320 + b * 20 + jj];
            float sgm = 1.0f / (1.0f + __expf(-gsum));
            if (r < 16) {
                g_z[(size_t)(b0 + b) * 512 + 32 * r + j] = sgm;
            } else {
                float rh = sgm * hpv[e];
                g_rh[(size_t)(b0 + b) * 512 + 32 * (r - 16) + j] = __uint_as_float(f2tf32(rh));
            }
        }
        barno++;
        group_barrier(g, barno * 32);

        // ---- phase B ----
        float zv = __ldcg(&g_z[(size_t)(b0 + cbb) * 512 + 16 * r + cjj]);
        {
            const float* src = g_rh + (size_t)b0 * 512;
#pragma unroll
            for (int s = tid; s < 2048; s += 256) {
                int b = s >> 7, c4 = s & 127;
                float4 v = __ldcg((const float4*)(src + (size_t)b * 512 + c4 * 4));
                *(float4*)(hS + b * LD_HS + c4 * 4) = v;
            }
        }
        __syncthreads();

        {
            float acc[2][4] = {};
#pragma unroll
            for (int ks = 0; ks < 8; ks++) {
                int k0 = w * 64 + ks * 8;
                unsigned a0 = __float_as_uint(hS[lg * LD_HS + k0 + tig]);
                unsigned a1 = __float_as_uint(hS[(lg + 8) * LD_HS + k0 + tig]);
                unsigned a2 = __float_as_uint(hS[lg * LD_HS + k0 + tig + 4]);
                unsigned a3 = __float_as_uint(hS[(lg + 8) * LD_HS + k0 + tig + 4]);
                mma_tf32(acc[0], a0, a1, a2, a3, bB[ks][0][0], bB[ks][0][1]);
                mma_tf32(acc[1], a0, a1, a2, a3, bB[ks][1][0], bB[ks][1][1]);
            }
            float* sw = scr + w * 320;
#pragma unroll
            for (int s = 0; s < 2; s++) {
                sw[lg * 20 + s * 8 + 2 * tig]           = acc[s][0];
                sw[lg * 20 + s * 8 + 2 * tig + 1]       = acc[s][1];
                sw[(lg + 8) * 20 + s * 8 + 2 * tig]     = acc[s][2];
                sw[(lg + 8) * 20 + s * 8 + 2 * tig + 1] = acc[s][3];
            }
        }
        __syncthreads();

        // ---- phase B epilogue: tanh, h update, outputs ----
        {
            float csum = xc + bcr;
#pragma unroll
            for (int ww = 0; ww < 8; ww++)
                csum += scr[ww * 320 + cbb * 20 + cjj];
            float cand = tanhf(csum);
            float hn = (1.0f - zv) * hreg + zv * cand;
            hreg = hn;
            size_t gidx = (size_t)(b0 + cbb) * 512 + 16 * r + cjj;
            out[(size_t)(t * 64 + b0 + cbb) * 512 + 16 * r + cjj] = hn;
            g_hcur[gidx] = hn;
            g_hA[gidx]   = __uint_as_float(f2tf32(hn));
            if (t == SEQ - 1)
                out[(size_t)SEQ * 64 * 512 + gidx] = hn;
        }
        barno++;
        group_barrier(g, barno * 32);
    }
}

// ---------------- launch ----------------
extern "C" void kernel_launch(void* const* d_in, const int* in_sizes, int n_in,
                              void* d_out, int out_size)
{
    const float* x  = (const float*)d_in[0];
    const float* h0 = (const float*)d_in[1];
    const float* Wg = (const float*)d_in[2];
    const float* bg = (const float*)d_in[3];
    const float* Wc = (const float*)d_in[4];
    const float* bc = (const float*)d_in[5];
    float* out = (float*)d_out;

    reset_kernel<<<128, 256>>>(h0);
    gemm_x_kernel<<<dim3(24, 1024), 256>>>(x, Wg, Wc);
    gru_scan_kernel<<<128, 256>>>(Wg, Wc, bg, bc, out);
}